// round 16
// baseline (speedup 1.0000x reference)
#include <cuda_runtime.h>
#include <cuda_fp16.h>
#include <cstdint>

#define B_    1024
#define T_    128
#define H_    512
#define RNNIN 128
#define LENV  1500
#define IPDV  256
#define EB    64
#define LAB   100

#define LDA  68
#define SMEM_BYTES (65536 + 2*32*LDA*4)   // sH(4 chunks x 16KB) + sAcc[2][32][68]

__device__ float  g_Wc[H_ * RNNIN];
__device__ float  g_c[H_];
__device__ float  g_Alen[LENV * H_];
__device__ float  g_Aipd[IPDV * H_];
__device__ __half g_W16[H_ * H_];                          // h2h_w [n][k] fp16
__device__ __align__(256) __half g_h16[2][4][1024][128];   // [buf][kchunk][row][128h] swizzled
__device__ float  g_hlast[B_ * H_];

// ---------------- kernel A: Wc = x2h_w @ fc1_w ; folded bias ----------------
__global__ void k_prep(const float* __restrict__ fc1_w, const float* __restrict__ fc1_b,
                       const float* __restrict__ x2h_w, const float* __restrict__ x2h_b,
                       const float* __restrict__ h2h_b) {
    __shared__ float s[RNNIN];
    int n = blockIdx.x, f = threadIdx.x;
    s[f] = x2h_w[n * RNNIN + f];
    __syncthreads();
    float acc = 0.f;
#pragma unroll 4
    for (int j = 0; j < RNNIN; ++j) acc += s[j] * fc1_w[j * 128 + f];
    g_Wc[n * RNNIN + f] = acc;
    if (f == 0) {
        float cb = x2h_b[n] + h2h_b[n];
        for (int j = 0; j < RNNIN; ++j) cb += s[j] * fc1_b[j];
        g_c[n] = cb;
    }
}

// ---------------- kernel B: fused embedding tables ----------------
#define RPB 16
__global__ void k_tables(const float* __restrict__ len_emb, const float* __restrict__ ipd_emb) {
    __shared__ float se[RPB][EB];
    int bid = blockIdx.x;
    const int lenBlocks = (LENV + RPB - 1) / RPB;
    bool isLen = bid < lenBlocks;
    int rbase, nrows, koff;
    const float* emb;
    float* dst;
    if (isLen) { rbase = bid * RPB;               nrows = LENV; koff = 0;  emb = len_emb; dst = g_Alen; }
    else       { rbase = (bid - lenBlocks) * RPB; nrows = IPDV; koff = EB; emb = ipd_emb; dst = g_Aipd; }
    for (int i = threadIdx.x; i < RPB * EB; i += blockDim.x) {
        int r = i / EB, k = i % EB;
        se[r][k] = (rbase + r < nrows) ? emb[(size_t)(rbase + r) * EB + k] : 0.f;
    }
    __syncthreads();
    int f = threadIdx.x;
    for (int q = 0; q < 4; ++q) {
        int n = q * 128 + f;
        float acc[RPB];
        float c0 = isLen ? g_c[n] : 0.f;
#pragma unroll
        for (int r = 0; r < RPB; ++r) acc[r] = c0;
        const float* wr = g_Wc + n * RNNIN + koff;
        for (int k = 0; k < EB; ++k) {
            float w = wr[k];
#pragma unroll
            for (int r = 0; r < RPB; ++r) acc[r] += w * se[r][k];
        }
        for (int r = 0; r < RPB; ++r)
            if (rbase + r < nrows) dst[(size_t)(rbase + r) * H_ + n] = acc[r];
    }
}

// ---------------- kernel C: h2h_w -> fp16 ----------------
__global__ void k_w16(const float* __restrict__ h2h_w) {
    int i = blockIdx.x * 256 + threadIdx.x;
    g_W16[i] = __float2half(h2h_w[i]);
}

// ---------------- helpers ----------------
__device__ __forceinline__ unsigned smem_u32(const void* p) {
    unsigned a;
    asm("{ .reg .u64 t; cvta.to.shared.u64 t, %1; cvt.u32.u64 %0, t; }" : "=r"(a) : "l"(p));
    return a;
}
__device__ __forceinline__ uint32_t h2_u32(__half2 h) {
    union { __half2 h; uint32_t u; } cv;
    cv.h = h;
    return cv.u;
}
__device__ __forceinline__ float ftanh(float x) {
    float e, r;
    asm("ex2.approx.f32 %0, %1;" : "=f"(e) : "f"(x * 2.885390081777927f));
    asm("rcp.approx.f32 %0, %1;" : "=f"(r) : "f"(e + 1.0f));
    return __fmaf_rn(-2.0f, r, 1.0f);
}
#define MBAR_INIT(a, c) asm volatile("mbarrier.init.shared.b64 [%0], %1;" :: "r"(a), "r"(c) : "memory")
#define MBAR_TX(a, b)   asm volatile("mbarrier.arrive.expect_tx.shared.b64 _, [%0], %1;" :: "r"(a), "r"(b) : "memory")
#define MBAR_WAIT(a, p) do { \
    asm volatile("{\n\t.reg .pred P;\n\tWL_%=:\n\t" \
        "mbarrier.try_wait.parity.acquire.cta.shared::cta.b64 P, [%0], %1, 0x989680;\n\t" \
        "@P bra.uni WD_%=;\n\tbra.uni WL_%=;\n\tWD_%=:\n\t}" :: "r"(a), "r"(p) : "memory"); } while (0)
#define BULK_G2S(d, s, n, m) \
    asm volatile("cp.async.bulk.shared::cta.global.mbarrier::complete_tx::bytes [%0], [%1], %2, [%3];" \
        :: "r"(d), "l"(s), "r"(n), "r"(m) : "memory")
#define FENCEA()  asm volatile("fence.proxy.async;" ::: "memory")
#define CARRIVE() asm volatile("barrier.cluster.arrive.aligned;" ::: "memory")
#define CWAIT()   asm volatile("barrier.cluster.wait.aligned;"   ::: "memory")

// ---------------- kernel D: recurrence (8-cluster, 128thr, 2 batch groups/CTA) ----------------
__global__ void __cluster_dims__(8, 1, 1) __launch_bounds__(128, 1)
k_rnn(const int* __restrict__ x) {
    extern __shared__ __half smem[];
    __shared__ __align__(8) unsigned long long mbar[4];
    char*  sB   = (char*)smem;                   // 4 chunks x [64 rows][256B] swizzled = 64KB
    float* sAcc = (float*)(sB + 65536);          // [2 grp][32][LDA]
    const unsigned sHu = smem_u32(sB);
    const unsigned mbu = smem_u32(mbar);

    const int rank = blockIdx.x & 7, cid = blockIdx.x >> 3;
    const int batch0 = cid * 64, n0 = rank * 64, tid = threadIdx.x;
    const int w = tid >> 5, lane = tid & 31;
    const int gid = lane >> 2, tig = lane & 3;
    const int r15 = lane & 15, g15 = lane >> 4;

    if (tid == 0) {
#pragma unroll
        for (int c = 0; c < 4; ++c) MBAR_INIT(mbu + 8 * c, 1);
    }
    __syncthreads();

    // persistent W fragments: 32 kk x 2 n8-tiles x 2 regs (warp covers 16 n-cols)
    uint32_t bw[32][2][2];
#pragma unroll
    for (int kk = 0; kk < 32; ++kk)
#pragma unroll
        for (int j = 0; j < 2; ++j) {
            const __half* wp = g_W16 + (size_t)(n0 + w * 16 + j * 8 + gid) * H_ + kk * 16 + tig * 2;
            bw[kk][j][0] = *(const uint32_t*)wp;
            bw[kk][j][1] = *(const uint32_t*)(wp + 8);
        }

    // epilogue mapping: 128 threads = 32 rows x 4 col-groups of 16
    const int er = tid >> 2, nl = (tid & 3) * 16;
    const int ebA = batch0 + er, ebB = batch0 + 32 + er;
    const int* xqA = x + (size_t)ebA * T_ * 2;
    const int* xqB = x + (size_t)ebB * T_ * 2;
    const unsigned sswz = (unsigned)(er & 15);
    const int u0 = (rank & 1) * 8 + (tid & 3) * 2;
    char* const hgA = (char*)g_h16 + (((size_t)(rank >> 1)) * 1024 + ebA) * 256;
    char* const hgB = (char*)g_h16 + (((size_t)(rank >> 1)) * 1024 + ebB) * 256;
    float4* const dlA = (float4*)(g_hlast + (size_t)ebA * H_ + n0 + nl);
    float4* const dlB = (float4*)(g_hlast + (size_t)ebB * H_ + n0 + nl);
    const unsigned su0 = ((unsigned)u0 ^ sswz) << 4;
    const unsigned su1 = ((unsigned)(u0 + 1) ^ sswz) << 4;

    float4 tl[4], ti[4];

    // ---------------- t = 0 (epilogue-only, h0 = 0; both groups) ----------------
    {
        uint32_t hv[8];
#pragma unroll
        for (int g = 0; g < 2; ++g) {
            const int* xq = g ? xqB : xqA;
            int i0 = xq[0], i1 = xq[1];
            const float4* pa = (const float4*)(g_Alen + (size_t)i0 * H_ + n0 + nl);
            const float4* pb = (const float4*)(g_Aipd + (size_t)i1 * H_ + n0 + nl);
#pragma unroll
            for (int j = 0; j < 4; ++j) {
                float4 l = pa[j], i4 = pb[j];
                float4 o;
                o.x = ftanh(l.x + i4.x);
                o.y = ftanh(l.y + i4.y);
                o.z = ftanh(l.z + i4.z);
                o.w = ftanh(l.w + i4.w);
                hv[j * 2]     = h2_u32(__floats2half2_rn(o.x, o.y));
                hv[j * 2 + 1] = h2_u32(__floats2half2_rn(o.z, o.w));
            }
            char* hg = g ? hgB : hgA;
            *(uint4*)(hg + su0) = ((uint4*)hv)[0];
            *(uint4*)(hg + su1) = ((uint4*)hv)[1];
        }
        FENCEA();
        CARRIVE(); CWAIT();
        if (tid == 0) {
#pragma unroll
            for (int c = 0; c < 4; ++c) {
                MBAR_TX(mbu + 8 * c, 16384);
                BULK_G2S(sHu + c * 16384,
                         (const char*)g_h16 + ((size_t)c * 1024 + batch0) * 256,
                         16384, mbu + 8 * c);
            }
        }
        // prefetch group-A tables for t=1 (hides under chunk0 L2 latency)
        int j0 = xqA[2], j1 = xqA[3];
        const float4* qa = (const float4*)(g_Alen + (size_t)j0 * H_ + n0 + nl);
        const float4* qb = (const float4*)(g_Aipd + (size_t)j1 * H_ + n0 + nl);
#pragma unroll
        for (int j = 0; j < 4; ++j) { tl[j] = qa[j]; ti[j] = qb[j]; }
    }

    // ---------------- t = 1 .. 127 ----------------
    for (int t = 1; t < T_; ++t) {
        const int p = (t - 1) & 1;
        const bool last = (t == T_ - 1);
        const size_t wgb = (size_t)(t & 1) * 1048576;
        float ac[2][2][4];

        // ======== GEMM group A (rows 0..31), chunk-pipelined ========
#pragma unroll
        for (int mt = 0; mt < 2; ++mt)
#pragma unroll
            for (int j = 0; j < 2; ++j)
#pragma unroll
                for (int q = 0; q < 4; ++q) ac[mt][j][q] = 0.f;
#pragma unroll
        for (int c = 0; c < 4; ++c) {
            MBAR_WAIT(mbu + 8 * c, p);
#pragma unroll
            for (int kc = 0; kc < 8; ++kc) {
#pragma unroll
                for (int mt = 0; mt < 2; ++mt) {
                    unsigned unit = ((unsigned)(2 * kc + g15) ^ (unsigned)r15) << 4;
                    unsigned ad = sHu + c * 16384 + (mt * 16 + r15) * 256 + unit;
                    uint32_t a0, a1, a2, a3;
                    asm volatile("ldmatrix.sync.aligned.m8n8.x4.shared.b16 {%0,%1,%2,%3}, [%4];"
                                 : "=r"(a0), "=r"(a1), "=r"(a2), "=r"(a3) : "r"(ad));
                    const int kk = c * 8 + kc;
#pragma unroll
                    for (int j = 0; j < 2; ++j)
                        asm volatile(
                            "mma.sync.aligned.m16n8k16.row.col.f32.f16.f16.f32 "
                            "{%0,%1,%2,%3},{%4,%5,%6,%7},{%8,%9},{%0,%1,%2,%3};"
                            : "+f"(ac[mt][j][0]), "+f"(ac[mt][j][1]),
                              "+f"(ac[mt][j][2]), "+f"(ac[mt][j][3])
                            : "r"(a0), "r"(a1), "r"(a2), "r"(a3),
                              "r"(bw[kk][j][0]), "r"(bw[kk][j][1]));
                }
            }
        }
#pragma unroll
        for (int mt = 0; mt < 2; ++mt)
#pragma unroll
            for (int j = 0; j < 2; ++j) {
                int n = w * 16 + j * 8 + tig * 2;
                float* p0 = sAcc + (mt * 16 + gid) * LDA + n;
                float* p1 = sAcc + (mt * 16 + gid + 8) * LDA + n;
                p0[0] = ac[mt][j][0]; p0[1] = ac[mt][j][1];
                p1[0] = ac[mt][j][2]; p1[1] = ac[mt][j][3];
            }
        __syncthreads();

        // ======== epilogue A ========
        {
            const float4* pq = (const float4*)(sAcc + er * LDA + nl);
            uint32_t hv[8];
            float4 fres[4];
#pragma unroll
            for (int j = 0; j < 4; ++j) {
                float4 qa = pq[j];
                float4 o;
                o.x = ftanh(qa.x + tl[j].x + ti[j].x);
                o.y = ftanh(qa.y + tl[j].y + ti[j].y);
                o.z = ftanh(qa.z + tl[j].z + ti[j].z);
                o.w = ftanh(qa.w + tl[j].w + ti[j].w);
                fres[j] = o;
                hv[j * 2]     = h2_u32(__floats2half2_rn(o.x, o.y));
                hv[j * 2 + 1] = h2_u32(__floats2half2_rn(o.z, o.w));
            }
            if (!last) {
                *(uint4*)(hgA + wgb + su0) = ((uint4*)hv)[0];
                *(uint4*)(hgA + wgb + su1) = ((uint4*)hv)[1];
            } else {
#pragma unroll
                for (int j = 0; j < 4; ++j) dlA[j] = fres[j];
            }
        }
        // prefetch group-B tables for this step (hides under GEMM B)
        {
            int j0 = xqB[2 * t], j1 = xqB[2 * t + 1];
            const float4* qa = (const float4*)(g_Alen + (size_t)j0 * H_ + n0 + nl);
            const float4* qb = (const float4*)(g_Aipd + (size_t)j1 * H_ + n0 + nl);
#pragma unroll
            for (int j = 0; j < 4; ++j) { tl[j] = qa[j]; ti[j] = qb[j]; }
        }

        // ======== GEMM group B (rows 32..63), all chunks already resident ========
#pragma unroll
        for (int mt = 0; mt < 2; ++mt)
#pragma unroll
            for (int j = 0; j < 2; ++j)
#pragma unroll
                for (int q = 0; q < 4; ++q) ac[mt][j][q] = 0.f;
#pragma unroll
        for (int c = 0; c < 4; ++c) {
#pragma unroll
            for (int kc = 0; kc < 8; ++kc) {
#pragma unroll
                for (int mt = 0; mt < 2; ++mt) {
                    unsigned unit = ((unsigned)(2 * kc + g15) ^ (unsigned)r15) << 4;
                    unsigned ad = sHu + c * 16384 + (32 + mt * 16 + r15) * 256 + unit;
                    uint32_t a0, a1, a2, a3;
                    asm volatile("ldmatrix.sync.aligned.m8n8.x4.shared.b16 {%0,%1,%2,%3}, [%4];"
                                 : "=r"(a0), "=r"(a1), "=r"(a2), "=r"(a3) : "r"(ad));
                    const int kk = c * 8 + kc;
#pragma unroll
                    for (int j = 0; j < 2; ++j)
                        asm volatile(
                            "mma.sync.aligned.m16n8k16.row.col.f32.f16.f16.f32 "
                            "{%0,%1,%2,%3},{%4,%5,%6,%7},{%8,%9},{%0,%1,%2,%3};"
                            : "+f"(ac[mt][j][0]), "+f"(ac[mt][j][1]),
                              "+f"(ac[mt][j][2]), "+f"(ac[mt][j][3])
                            : "r"(a0), "r"(a1), "r"(a2), "r"(a3),
                              "r"(bw[kk][j][0]), "r"(bw[kk][j][1]));
                }
            }
        }
#pragma unroll
        for (int mt = 0; mt < 2; ++mt)
#pragma unroll
            for (int j = 0; j < 2; ++j) {
                int n = w * 16 + j * 8 + tig * 2;
                float* p0 = sAcc + (32 + mt * 16 + gid) * LDA + n;
                float* p1 = sAcc + (32 + mt * 16 + gid + 8) * LDA + n;
                p0[0] = ac[mt][j][0]; p0[1] = ac[mt][j][1];
                p1[0] = ac[mt][j][2]; p1[1] = ac[mt][j][3];
            }
        __syncthreads();

        // ======== epilogue B ========
        {
            const float4* pq = (const float4*)(sAcc + (32 + er) * LDA + nl);
            uint32_t hv[8];
            float4 fres[4];
#pragma unroll
            for (int j = 0; j < 4; ++j) {
                float4 qa = pq[j];
                float4 o;
                o.x = ftanh(qa.x + tl[j].x + ti[j].x);
                o.y = ftanh(qa.y + tl[j].y + ti[j].y);
                o.z = ftanh(qa.z + tl[j].z + ti[j].z);
                o.w = ftanh(qa.w + tl[j].w + ti[j].w);
                fres[j] = o;
                hv[j * 2]     = h2_u32(__floats2half2_rn(o.x, o.y));
                hv[j * 2 + 1] = h2_u32(__floats2half2_rn(o.z, o.w));
            }
            if (!last) {
                *(uint4*)(hgB + wgb + su0) = ((uint4*)hv)[0];
                *(uint4*)(hgB + wgb + su1) = ((uint4*)hv)[1];
            } else {
#pragma unroll
                for (int j = 0; j < 4; ++j) dlB[j] = fres[j];
            }
        }

        if (!last) {
            FENCEA();
            CARRIVE(); CWAIT();
            if (tid == 0) {
#pragma unroll
                for (int c = 0; c < 4; ++c) {
                    MBAR_TX(mbu + 8 * c, 16384);
                    BULK_G2S(sHu + c * 16384,
                             (const char*)g_h16 + wgb + ((size_t)c * 1024 + batch0) * 256,
                             16384, mbu + 8 * c);
                }
            }
            // prefetch group-A tables for t+1 (hides under chunk0 latency)
            int j0 = xqA[2 * (t + 1)], j1 = xqA[2 * (t + 1) + 1];
            const float4* qa = (const float4*)(g_Alen + (size_t)j0 * H_ + n0 + nl);
            const float4* qb = (const float4*)(g_Aipd + (size_t)j1 * H_ + n0 + nl);
#pragma unroll
            for (int j = 0; j < 4; ++j) { tl[j] = qa[j]; ti[j] = qb[j]; }
        }
    }
}

// ---------------- kernel E: fc2 ----------------
__global__ void k_fc2(const float* __restrict__ fc2_w, const float* __restrict__ fc2_b,
                      float* __restrict__ out) {
    __shared__ float sh[16][H_];
    int batch0 = blockIdx.x * 16;
    for (int i = threadIdx.x; i < 16 * H_; i += 256) {
        int r = i >> 9, k = i & (H_ - 1);
        sh[r][k] = g_hlast[(size_t)(batch0 + r) * H_ + k];
    }
    __syncthreads();
    int tid = threadIdx.x;
    if (tid < 200) {
        int l = tid % 100, bh = tid / 100;
        float acc[8];
        float bias = fc2_b[l];
#pragma unroll
        for (int i = 0; i < 8; ++i) acc[i] = bias;
        const float4* wr = (const float4*)(fc2_w + (size_t)l * H_);
        for (int k4 = 0; k4 < H_ / 4; ++k4) {
            float4 wv = wr[k4];
#pragma unroll
            for (int i = 0; i < 8; ++i) {
                float4 h = *(const float4*)(&sh[bh * 8 + i][k4 * 4]);
                acc[i] += wv.x * h.x + wv.y * h.y + wv.z * h.z + wv.w * h.w;
            }
        }
        for (int i = 0; i < 8; ++i)
            out[(size_t)(batch0 + bh * 8 + i) * LAB + l] = acc[i];
    }
}

// ---------------- launch ----------------
extern "C" void kernel_launch(void* const* d_in, const int* in_sizes, int n_in,
                              void* d_out, int out_size) {
    const int* x         = (const int*)d_in[0];
    const float* len_emb = (const float*)d_in[1];
    const float* ipd_emb = (const float*)d_in[2];
    const float* fc1_w   = (const float*)d_in[3];
    const float* fc1_b   = (const float*)d_in[4];
    const float* x2h_w   = (const float*)d_in[5];
    const float* x2h_b   = (const float*)d_in[6];
    const float* h2h_w   = (const float*)d_in[7];
    const float* h2h_b   = (const float*)d_in[8];
    const float* fc2_w   = (const float*)d_in[9];
    const float* fc2_b   = (const float*)d_in[10];
    float* out = (float*)d_out;

    cudaFuncSetAttribute(k_rnn, cudaFuncAttributeMaxDynamicSharedMemorySize, SMEM_BYTES);

    k_prep  <<<512, 128>>>(fc1_w, fc1_b, x2h_w, x2h_b, h2h_b);
    k_tables<<<(LENV + RPB - 1) / RPB + IPDV / RPB, 128>>>(len_emb, ipd_emb);
    k_w16   <<<H_ * H_ / 256, 256>>>(h2h_w);
    k_rnn   <<<128, 128, SMEM_BYTES>>>(x);
    k_fc2   <<<B_ / 16, 256>>>(fc2_w, fc2_b, out);
}

// round 17
// speedup vs baseline: 1.5603x; 1.5603x over previous
#include <cuda_runtime.h>
#include <cuda_fp16.h>
#include <cstdint>

#define B_    1024
#define T_    128
#define H_    512
#define RNNIN 128
#define LENV  1500
#define IPDV  256
#define EB    64
#define LAB   100

#define LDA  68
#define SMEM_BYTES (32768 + 32*LDA*4)

__device__ float  g_Wc[H_ * RNNIN];
__device__ float  g_c[H_];
__device__ float  g_Alen[LENV * H_];
__device__ float  g_Aipd[IPDV * H_];
__device__ __half g_W16[H_ * H_];                          // h2h_w [n][k] fp16
__device__ __align__(256) __half g_h16[2][4][1024][128];   // [buf][kchunk][row][128h] swizzled
__device__ float  g_hlast[B_ * H_];

// ---------------- kernel A: Wc = x2h_w @ fc1_w ; folded bias ; W16 convert ----------------
__global__ void k_prep(const float* __restrict__ fc1_w, const float* __restrict__ fc1_b,
                       const float* __restrict__ x2h_w, const float* __restrict__ x2h_b,
                       const float* __restrict__ h2h_b, const float* __restrict__ h2h_w) {
    __shared__ float s[RNNIN];
    int n = blockIdx.x, f = threadIdx.x;
    s[f] = x2h_w[n * RNNIN + f];
    __syncthreads();
    float acc = 0.f;
#pragma unroll 4
    for (int j = 0; j < RNNIN; ++j) acc += s[j] * fc1_w[j * 128 + f];
    g_Wc[n * RNNIN + f] = acc;
    if (f == 0) {
        float cb = x2h_b[n] + h2h_b[n];
        for (int j = 0; j < RNNIN; ++j) cb += s[j] * fc1_b[j];
        g_c[n] = cb;
    }
    // fold in W16 conversion: row n of h2h_w -> fp16 (4 elems/thread)
    const float4 wv = *(const float4*)(h2h_w + (size_t)n * H_ + f * 4);
    __half2 h0 = __floats2half2_rn(wv.x, wv.y);
    __half2 h1 = __floats2half2_rn(wv.z, wv.w);
    *(__half2*)(g_W16 + (size_t)n * H_ + f * 4)     = h0;
    *(__half2*)(g_W16 + (size_t)n * H_ + f * 4 + 2) = h1;
}

// ---------------- kernel B: fused embedding tables (smem-tiled Wc) ----------------
#define RPB 16
__global__ void k_tables(const float* __restrict__ len_emb, const float* __restrict__ ipd_emb) {
    __shared__ float se[RPB][EB];
    __shared__ float sw[128][EB + 1];
    int bid = blockIdx.x;
    const int lenBlocks = (LENV + RPB - 1) / RPB;
    bool isLen = bid < lenBlocks;
    int rbase, nrows, koff;
    const float* emb;
    float* dst;
    if (isLen) { rbase = bid * RPB;               nrows = LENV; koff = 0;  emb = len_emb; dst = g_Alen; }
    else       { rbase = (bid - lenBlocks) * RPB; nrows = IPDV; koff = EB; emb = ipd_emb; dst = g_Aipd; }
    for (int i = threadIdx.x; i < RPB * EB; i += blockDim.x) {
        int r = i / EB, k = i % EB;
        se[r][k] = (rbase + r < nrows) ? emb[(size_t)(rbase + r) * EB + k] : 0.f;
    }
    int f = threadIdx.x;
    for (int q = 0; q < 4; ++q) {
        // coalesced tile load: rows q*128..q*128+127, cols koff..koff+63
        __syncthreads();   // protect sw reuse across q (and se on q=0)
        for (int i = f; i < 128 * 16; i += 128) {
            int row = i >> 4, kq = i & 15;
            float4 v = *(const float4*)(g_Wc + (size_t)(q * 128 + row) * RNNIN + koff + kq * 4);
            sw[row][kq * 4]     = v.x;
            sw[row][kq * 4 + 1] = v.y;
            sw[row][kq * 4 + 2] = v.z;
            sw[row][kq * 4 + 3] = v.w;
        }
        __syncthreads();
        int n = q * 128 + f;
        float acc[RPB];
        float c0 = isLen ? g_c[n] : 0.f;
#pragma unroll
        for (int r = 0; r < RPB; ++r) acc[r] = c0;
        for (int k = 0; k < EB; ++k) {
            float w = sw[f][k];
#pragma unroll
            for (int r = 0; r < RPB; ++r) acc[r] += w * se[r][k];
        }
        for (int r = 0; r < RPB; ++r)
            if (rbase + r < nrows) dst[(size_t)(rbase + r) * H_ + n] = acc[r];
    }
}

// ---------------- helpers ----------------
__device__ __forceinline__ unsigned smem_u32(const void* p) {
    unsigned a;
    asm("{ .reg .u64 t; cvta.to.shared.u64 t, %1; cvt.u32.u64 %0, t; }" : "=r"(a) : "l"(p));
    return a;
}
__device__ __forceinline__ uint32_t h2_u32(__half2 h) {
    union { __half2 h; uint32_t u; } cv;
    cv.h = h;
    return cv.u;
}
__device__ __forceinline__ float ftanh(float x) {
    float e, r;
    asm("ex2.approx.f32 %0, %1;" : "=f"(e) : "f"(x * 2.885390081777927f));
    asm("rcp.approx.f32 %0, %1;" : "=f"(r) : "f"(e + 1.0f));
    return __fmaf_rn(-2.0f, r, 1.0f);
}
#define MBAR_INIT(a, c) asm volatile("mbarrier.init.shared.b64 [%0], %1;" :: "r"(a), "r"(c) : "memory")
#define MBAR_TX(a, b)   asm volatile("mbarrier.arrive.expect_tx.shared.b64 _, [%0], %1;" :: "r"(a), "r"(b) : "memory")
#define MBAR_WAIT(a, p) do { \
    asm volatile("{\n\t.reg .pred P;\n\tWL_%=:\n\t" \
        "mbarrier.try_wait.parity.acquire.cta.shared::cta.b64 P, [%0], %1, 0x989680;\n\t" \
        "@P bra.uni WD_%=;\n\tbra.uni WL_%=;\n\tWD_%=:\n\t}" :: "r"(a), "r"(p) : "memory"); } while (0)
#define BULK_G2S(d, s, n, m) \
    asm volatile("cp.async.bulk.shared::cta.global.mbarrier::complete_tx::bytes [%0], [%1], %2, [%3];" \
        :: "r"(d), "l"(s), "r"(n), "r"(m) : "memory")

// ---------------- kernel D: recurrence (8-CTA cluster, 128-thread CTAs) ----------------
__global__ void __cluster_dims__(8, 1, 1) __launch_bounds__(128, 2)
k_rnn(const int* __restrict__ x) {
    extern __shared__ __half smem[];
    __shared__ __align__(8) unsigned long long mbar[4];
    __half* sH   = smem;                        // 4 chunks x [32 rows][128h] swizzled = 32KB
    float*  sAcc = (float*)(smem + 16384);      // [32][LDA]
    const unsigned sHu = smem_u32(sH);
    const unsigned mbu = smem_u32(mbar);

    const int rank = blockIdx.x & 7, cid = blockIdx.x >> 3;
    const int batch0 = cid * 32, n0 = rank * 64, tid = threadIdx.x;
    const int w = tid >> 5, lane = tid & 31;
    const int gid = lane >> 2, tig = lane & 3;
    const int nw = n0 + w * 16;
    const int r15 = lane & 15, g15 = lane >> 4;

    if (tid == 0) {
#pragma unroll
        for (int c = 0; c < 4; ++c) MBAR_INIT(mbu + 8 * c, 1);
    }
    __syncthreads();

    uint32_t bw[32][2][2];
#pragma unroll
    for (int kk = 0; kk < 32; ++kk)
#pragma unroll
        for (int j = 0; j < 2; ++j) {
            const __half* wp = g_W16 + (size_t)(nw + j * 8 + gid) * H_ + kk * 16 + tig * 2;
            bw[kk][j][0] = *(const uint32_t*)wp;
            bw[kk][j][1] = *(const uint32_t*)(wp + 8);
        }

    const int er = tid >> 2, nl = (tid & 3) * 16;
    const int eb = batch0 + er;
    const int* xp = x + (size_t)eb * T_ * 2;
    const unsigned sswz = (unsigned)(er & 15);
    const int u0 = (rank & 1) * 8 + (tid & 3) * 2;
    char* const hrow0 = (char*)g_h16 + (((size_t)(rank >> 1)) * 1024 + eb) * 256;
    float4* const dlast = (float4*)(g_hlast + (size_t)eb * H_ + n0 + nl);

    // ---------------- t = 0 (epilogue-only, h0 = 0) ----------------
    float4 tl[4], ti[4];
    {
        int i0 = xp[0], i1 = xp[1];
        const float4* pa = (const float4*)(g_Alen + (size_t)i0 * H_ + n0 + nl);
        const float4* pb = (const float4*)(g_Aipd + (size_t)i1 * H_ + n0 + nl);
#pragma unroll
        for (int j = 0; j < 4; ++j) { tl[j] = pa[j]; ti[j] = pb[j]; }
        uint32_t hv[8];
#pragma unroll
        for (int j = 0; j < 4; ++j) {
            float4 o;
            o.x = ftanh(tl[j].x + ti[j].x);
            o.y = ftanh(tl[j].y + ti[j].y);
            o.z = ftanh(tl[j].z + ti[j].z);
            o.w = ftanh(tl[j].w + ti[j].w);
            hv[j * 2]     = h2_u32(__floats2half2_rn(o.x, o.y));
            hv[j * 2 + 1] = h2_u32(__floats2half2_rn(o.z, o.w));
        }
        *(uint4*)(hrow0 + (((unsigned)u0 ^ sswz) << 4))       = ((uint4*)hv)[0];
        *(uint4*)(hrow0 + (((unsigned)(u0 + 1) ^ sswz) << 4)) = ((uint4*)hv)[1];
        int j0 = xp[2], j1 = xp[3];
        const float4* qa = (const float4*)(g_Alen + (size_t)j0 * H_ + n0 + nl);
        const float4* qb = (const float4*)(g_Aipd + (size_t)j1 * H_ + n0 + nl);
#pragma unroll
        for (int j = 0; j < 4; ++j) { tl[j] = qa[j]; ti[j] = qb[j]; }
        asm volatile("fence.proxy.async;" ::: "memory");
        asm volatile("barrier.cluster.arrive.aligned;" ::: "memory");
        asm volatile("barrier.cluster.wait.aligned;"   ::: "memory");
    }

    // ---------------- t = 1 .. 127 ----------------
    for (int t = 1; t < T_; ++t) {
        const int rb = (t - 1) & 1, p = (t - 1) & 1;

        if (tid == 0) {
#pragma unroll
            for (int c = 0; c < 4; ++c) {
                MBAR_TX(mbu + 8 * c, 8192);
                BULK_G2S(sHu + c * 8192,
                         (const char*)g_h16 + (((size_t)rb * 4 + c) * 1024 + batch0) * 256,
                         8192, mbu + 8 * c);
            }
        }

        float ac[2][2][4];
#pragma unroll
        for (int mt = 0; mt < 2; ++mt)
#pragma unroll
            for (int j = 0; j < 2; ++j)
#pragma unroll
                for (int q = 0; q < 4; ++q) ac[mt][j][q] = 0.f;

#pragma unroll
        for (int c = 0; c < 4; ++c) {
            MBAR_WAIT(mbu + 8 * c, p);
#pragma unroll
            for (int kc = 0; kc < 8; ++kc) {
#pragma unroll
                for (int mt = 0; mt < 2; ++mt) {
                    unsigned unit = ((unsigned)(2 * kc + g15) ^ (unsigned)r15) << 4;
                    unsigned ad = sHu + c * 8192 + (mt * 16 + r15) * 256 + unit;
                    uint32_t a0, a1, a2, a3;
                    asm volatile("ldmatrix.sync.aligned.m8n8.x4.shared.b16 {%0,%1,%2,%3}, [%4];"
                                 : "=r"(a0), "=r"(a1), "=r"(a2), "=r"(a3) : "r"(ad));
                    const int kk = c * 8 + kc;
#pragma unroll
                    for (int j = 0; j < 2; ++j)
                        asm volatile(
                            "mma.sync.aligned.m16n8k16.row.col.f32.f16.f16.f32 "
                            "{%0,%1,%2,%3},{%4,%5,%6,%7},{%8,%9},{%0,%1,%2,%3};"
                            : "+f"(ac[mt][j][0]), "+f"(ac[mt][j][1]),
                              "+f"(ac[mt][j][2]), "+f"(ac[mt][j][3])
                            : "r"(a0), "r"(a1), "r"(a2), "r"(a3),
                              "r"(bw[kk][j][0]), "r"(bw[kk][j][1]));
                }
            }
        }

#pragma unroll
        for (int mt = 0; mt < 2; ++mt)
#pragma unroll
            for (int j = 0; j < 2; ++j) {
                int n = w * 16 + j * 8 + tig * 2;
                float* p0 = sAcc + (mt * 16 + gid) * LDA + n;
                float* p1 = sAcc + (mt * 16 + gid + 8) * LDA + n;
                p0[0] = ac[mt][j][0]; p0[1] = ac[mt][j][1];
                p1[0] = ac[mt][j][2]; p1[1] = ac[mt][j][3];
            }
        __syncthreads();

        const float4* pq = (const float4*)(sAcc + er * LDA + nl);
        uint32_t hv[8];
        float4 fres[4];
#pragma unroll
        for (int j = 0; j < 4; ++j) {
            float4 qa = pq[j];
            float4 o;
            o.x = ftanh(qa.x + tl[j].x + ti[j].x);
            o.y = ftanh(qa.y + tl[j].y + ti[j].y);
            o.z = ftanh(qa.z + tl[j].z + ti[j].z);
            o.w = ftanh(qa.w + tl[j].w + ti[j].w);
            fres[j] = o;
            hv[j * 2]     = h2_u32(__floats2half2_rn(o.x, o.y));
            hv[j * 2 + 1] = h2_u32(__floats2half2_rn(o.z, o.w));
        }
        if (t < T_ - 1) {
            char* hrow = hrow0 + (size_t)(t & 1) * (4u * 1024u * 256u);
            *(uint4*)(hrow + (((unsigned)u0 ^ sswz) << 4))       = ((uint4*)hv)[0];
            *(uint4*)(hrow + (((unsigned)(u0 + 1) ^ sswz) << 4)) = ((uint4*)hv)[1];
            int j0 = xp[2 * (t + 1)], j1 = xp[2 * (t + 1) + 1];
            const float4* qa2 = (const float4*)(g_Alen + (size_t)j0 * H_ + n0 + nl);
            const float4* qb2 = (const float4*)(g_Aipd + (size_t)j1 * H_ + n0 + nl);
#pragma unroll
            for (int j = 0; j < 4; ++j) { tl[j] = qa2[j]; ti[j] = qb2[j]; }
            asm volatile("fence.proxy.async;" ::: "memory");
            asm volatile("barrier.cluster.arrive.aligned;" ::: "memory");
            asm volatile("barrier.cluster.wait.aligned;"   ::: "memory");
        } else {
#pragma unroll
            for (int j = 0; j < 4; ++j) dlast[j] = fres[j];
        }
    }
}

// ---------------- kernel E: fc2 ----------------
__global__ void k_fc2(const float* __restrict__ fc2_w, const float* __restrict__ fc2_b,
                      float* __restrict__ out) {
    __shared__ float sh[16][H_];
    int batch0 = blockIdx.x * 16;
    for (int i = threadIdx.x; i < 16 * H_; i += 256) {
        int r = i >> 9, k = i & (H_ - 1);
        sh[r][k] = g_hlast[(size_t)(batch0 + r) * H_ + k];
    }
    __syncthreads();
    int tid = threadIdx.x;
    if (tid < 200) {
        int l = tid % 100, bh = tid / 100;
        float acc[8];
        float bias = fc2_b[l];
#pragma unroll
        for (int i = 0; i < 8; ++i) acc[i] = bias;
        const float4* wr = (const float4*)(fc2_w + (size_t)l * H_);
        for (int k4 = 0; k4 < H_ / 4; ++k4) {
            float4 wv = wr[k4];
#pragma unroll
            for (int i = 0; i < 8; ++i) {
                float4 h = *(const float4*)(&sh[bh * 8 + i][k4 * 4]);
                acc[i] += wv.x * h.x + wv.y * h.y + wv.z * h.z + wv.w * h.w;
            }
        }
        for (int i = 0; i < 8; ++i)
            out[(size_t)(batch0 + bh * 8 + i) * LAB + l] = acc[i];
    }
}

// ---------------- launch ----------------
extern "C" void kernel_launch(void* const* d_in, const int* in_sizes, int n_in,
                              void* d_out, int out_size) {
    const int* x         = (const int*)d_in[0];
    const float* len_emb = (const float*)d_in[1];
    const float* ipd_emb = (const float*)d_in[2];
    const float* fc1_w   = (const float*)d_in[3];
    const float* fc1_b   = (const float*)d_in[4];
    const float* x2h_w   = (const float*)d_in[5];
    const float* x2h_b   = (const float*)d_in[6];
    const float* h2h_w   = (const float*)d_in[7];
    const float* h2h_b   = (const float*)d_in[8];
    const float* fc2_w   = (const float*)d_in[9];
    const float* fc2_b   = (const float*)d_in[10];
    float* out = (float*)d_out;

    cudaFuncSetAttribute(k_rnn, cudaFuncAttributeMaxDynamicSharedMemorySize, SMEM_BYTES);

    k_prep  <<<512, 128>>>(fc1_w, fc1_b, x2h_w, x2h_b, h2h_b, h2h_w);
    k_tables<<<(LENV + RPB - 1) / RPB + IPDV / RPB, 128>>>(len_emb, ipd_emb);
    k_rnn   <<<256, 128, SMEM_BYTES>>>(x);
    k_fc2   <<<B_ / 16, 256>>>(fc2_w, fc2_b, out);
}